// round 12
// baseline (speedup 1.0000x reference)
#include <cuda_runtime.h>
#include <cuda_fp16.h>

// Fused AA max-pool: up2+FIR7 -> maxpool5x5 s1 -> FIR7+down4.
// One CTA = TWO (n,c) images x 8 output rows, 256 threads (8 warps).
// Stages 1+2 fully fused in registers: vertical up-FIR streams global rows,
// packs (row 2q, 2q+1) as half2; horizontal neighbors come from 3 warp
// shuffles per pack (warp = 28 productive cols + 4 halo lanes); rolling
// packed 5-row max -> sM (only smem array). Stage 3 unchanged from R10.

#define WIN  112
#define TI   8
#define WMS2 232                 // sM row stride (words); col v at word v+4
#define PM   18                  // M packs (rows 0..35)
#define M_WORDS (PM*WMS2)        // 4176
#define HOUT 56
#define WOUT 56
#define NTHREADS 256
#define SMEM_WORDS (2*M_WORDS)   // 8352 words = 33408 B -> 5 CTAs/SM (reg cap 51)

__device__ __forceinline__ int swz(int c) { return c ^ (((c >> 5) & 1) << 2); }

__device__ __forceinline__ __half2 h2shift(__half2 a, __half2 b) {
    unsigned r = __byte_perm(*(unsigned*)&a, *(unsigned*)&b, 0x5432);
    return *(__half2*)&r;
}

// ---- fused stages 1+2, templated on EDGE row handling ----
template<bool EDGE>
__device__ __forceinline__ void stage12(
    unsigned* __restrict__ sMh, const float* __restrict__ x,
    int nc0, int t, int in_row0, int u0,
    float f0, float f1, float f2, float f3, float f4, float f5, float f6,
    __half2 f0h, __half2 f1h, __half2 f2h, __half2 f3h,
    __half2 f4h, __half2 f5h, __half2 f6h)
{
    const unsigned NEG2U = 0xFC00FC00u;
    const __half2 NEG2 = *(const __half2*)&NEG2U;

    const int wid = t >> 5, lane = t & 31;
    const int img = wid >> 2;                 // warps 0-3 img0, 4-7 img1
    const int wk  = wid & 3;
    const int c   = 28*wk - 1 + lane;         // A col, -1..114
    const bool real  = ((unsigned)c < 112u);
    const bool emits = (lane >= 1) && (lane <= 28);
    const __half2 zmask = real ? __float2half2_rn(1.f) : __float2half2_rn(0.f);
    const float* col = x + (size_t)(nc0 + img)*(WIN*WIN) + (real ? c : 0);
    unsigned* mrow = sMh + img*M_WORDS + swz(2*c + 4);   // col pair (2c,2c+1)

    int jlo = 0, jhi = 20;
    if (EDGE) {
        int v = (0 - u0) > 0 ? (0 - u0) : 0;
        jlo = v >> 1;
        jhi = (224 - u0) >> 1; if (jhi > 20) jhi = 20;
    }

    float x0, x1, x2;
    if (EDGE) {
        int r;
        r = in_row0;     x0 = (r>=0 && r<WIN) ? col[r*WIN] : 0.f;
        r = in_row0 + 1; x1 = (r>=0 && r<WIN) ? col[r*WIN] : 0.f;
        r = in_row0 + 2; x2 = (r>=0 && r<WIN) ? col[r*WIN] : 0.f;
    } else {
        x0 = col[in_row0*WIN];
        x1 = col[(in_row0+1)*WIN];
        x2 = col[(in_row0+2)*WIN];
    }

    __half2 PeP = NEG2, PoP = NEG2, AeP = NEG2, AoP = NEG2;
#pragma unroll
    for (int j = 0; j < 20; j++) {
        int r = in_row0 + j + 3;
        float x3;
        if (EDGE) x3 = (r>=0 && r<WIN) ? col[r*WIN] : 0.f;
        else      x3 = col[r*WIN];
        // vertical up-2 FIR -> A pack for this column (rows 2j, 2j+1)
        float ae = f1*x0 + f3*x1 + f5*x2;
        float ao = f0*x0 + f2*x1 + f4*x2 + f6*x3;
        __half2 a1 = __hmul2(__floats2half2_rn(ae, ao), zmask);  // halo cols -> 0
        unsigned a1u = *(unsigned*)&a1;
        unsigned a0u = __shfl_up_sync  (0xffffffffu, a1u, 1);    // col c-1
        unsigned a2u = __shfl_down_sync(0xffffffffu, a1u, 1);    // col c+1
        unsigned a3u = __shfl_down_sync(0xffffffffu, a1u, 2);    // col c+2
        __half2 a0 = *(__half2*)&a0u, a2 = *(__half2*)&a2u, a3 = *(__half2*)&a3u;
        // horizontal up-2 FIR (both phases), 2 rows at once
        __half2 be = __hfma2(f5h,a2, __hfma2(f3h,a1, __hmul2(f1h,a0)));
        __half2 bo = __hfma2(f6h,a3, __hfma2(f4h,a2,
                      __hfma2(f2h,a1, __hmul2(f0h,a0))));
        __half2 Pe, Po;
        if (EDGE) {
            bool valid = (j >= jlo) && (j < jhi);
            Pe = valid ? be : NEG2;
            Po = valid ? bo : NEG2;
        } else { Pe = be; Po = bo; }
        // packed rolling 5-row max
        __half2 Ae = __hmax2(PeP, h2shift(PeP, Pe));
        __half2 Ao = __hmax2(PoP, h2shift(PoP, Po));
        if (j >= 2 && emits) {
            __half2 Me = __hmax2(AeP, __hmax2(Ae, Pe));
            __half2 Mo = __hmax2(AoP, __hmax2(Ao, Po));
            uint2 mm = make_uint2(*(unsigned*)&Me, *(unsigned*)&Mo);
            *reinterpret_cast<uint2*>(mrow + (j - 2)*WMS2) = mm;
        }
        AeP = Ae; AoP = Ao; PeP = Pe; PoP = Po;
        x0 = x1; x1 = x2; x2 = x3;
    }
}

__global__ void __launch_bounds__(NTHREADS, 5)
aamaxpool_fused_kernel(const float* __restrict__ x,
                       const float* __restrict__ fpre,
                       const float* __restrict__ fpost,
                       float* __restrict__ out)
{
    extern __shared__ unsigned smu[];
    unsigned* sMh = smu;

    const int t  = threadIdx.x;
    const int i0 = blockIdx.x * TI;
    const int nc0 = 2 * blockIdx.y;
    const int in_row0 = 2*i0 - 3;
    const int u0 = 4*i0 - 4;
    const int r0 = 4*i0 - 3;
    const unsigned NEG2U = 0xFC00FC00u;
    const bool edge = (blockIdx.x == 0) | (blockIdx.x == 6);

    const float f0=__ldg(fpre+0), f1=__ldg(fpre+1), f2=__ldg(fpre+2),
                f3=__ldg(fpre+3), f4=__ldg(fpre+4), f5=__ldg(fpre+5),
                f6=__ldg(fpre+6);
    const __half2 f0h=__float2half2_rn(f0), f1h=__float2half2_rn(f1),
                  f2h=__float2half2_rn(f2), f3h=__float2half2_rn(f3),
                  f4h=__float2half2_rn(f4), f5h=__float2half2_rn(f5),
                  f6h=__float2half2_rn(f6);

    // ---- sM halo pads: colwords {0..3, 228..231} x 18 packs x 2 imgs ----
    for (int idx = t; idx < 2*PM*8; idx += NTHREADS) {
        int im = idx / (PM*8), rem = idx - im*(PM*8);
        int jm = rem >> 3, k = rem & 7;
        int c = (k < 4) ? k : 224 + k;
        sMh[im*M_WORDS + jm*WMS2 + swz(c)] = NEG2U;
    }

    if (edge) {
        stage12<true >(sMh, x, nc0, t, in_row0, u0,
                       f0,f1,f2,f3,f4,f5,f6, f0h,f1h,f2h,f3h,f4h,f5h,f6h);
        __syncthreads();
        // edge fix-up: zero M rows with rg outside [0,222) (FIR zero-pad)
        int btop = (-r0 > 0) ? -r0 : 0;
        int lc0 = 222 - r0; if (lc0 > 35) lc0 = 35;
        if (btop > 0 || lc0 < 35) {
            for (int idx = t; idx < 2*WMS2; idx += NTHREADS) {
                int im = idx / WMS2, c = idx - WMS2*im;
                unsigned* Mi = sMh + im*M_WORDS;
                int cw = swz(c);
                for (int lc = 0; lc < btop; lc++)
                    ((unsigned short*)(Mi + (lc>>1)*WMS2 + cw))[lc & 1] = 0;
                for (int lc = lc0; lc < 35; lc++)
                    ((unsigned short*)(Mi + (lc>>1)*WMS2 + cw))[lc & 1] = 0;
            }
        }
        __syncthreads();
    } else {
        stage12<false>(sMh, x, nc0, t, in_row0, u0,
                       f0,f1,f2,f3,f4,f5,f6, f0h,f1h,f2h,f3h,f4h,f5h,f6h);
        __syncthreads();
    }

    // ---- stage 3: packed 5-col max + vertical FIR + shfl horizontal FIR ----
    {
        float g[7];
#pragma unroll
        for (int i = 0; i < 7; i++) g[i] = __ldg(fpost + i);

        const int wid = t >> 5, lane = t & 31;
        const int img = wid >> 2;                  // warps 0-3 img0, 4-7 img1
        const int lp  = wid & 3;                   // output rows 2lp, 2lp+1
        const int q   = (lane < 28) ? lane : 27;
        const unsigned* Mi = sMh + img*M_WORDS;
        float d0[8] = {0,0,0,0,0,0,0,0};
        float d1[8] = {0,0,0,0,0,0,0,0};
#pragma unroll
        for (int pp = 0; pp < 6; pp++) {
            const int pg = 4*lp + pp;
            const unsigned* base = Mi + pg*WMS2;
            unsigned Cw[16];
#pragma unroll
            for (int gi = 0; gi < 4; gi++) {
                uint4 v = *reinterpret_cast<const uint4*>(base + swz(8*q + 4*gi));
                Cw[4*gi+0] = v.x; Cw[4*gi+1] = v.y; Cw[4*gi+2] = v.z; Cw[4*gi+3] = v.w;
            }
            __half2 C[16];
#pragma unroll
            for (int i = 0; i < 16; i++) C[i] = *(__half2*)&Cw[i];
            __half2 p[10];                          // p[i-3] = max(C[i],C[i+1])
#pragma unroll
            for (int i = 0; i < 10; i++) p[i] = __hmax2(C[i+3], C[i+4]);
#pragma unroll
            for (int k = 0; k < 8; k++) {
                __half2 wmx = __hmax2(p[k], __hmax2(p[k+2], C[k+7]));
                float lo = __low2float(wmx);
                float hi = __high2float(wmx);
                if (pp == 0)      { d0[k] += g[0]*lo + g[1]*hi; }
                else if (pp == 1) { d0[k] += g[2]*lo + g[3]*hi; }
                else if (pp == 2) { d0[k] += g[4]*lo + g[5]*hi;
                                    d1[k] += g[0]*lo + g[1]*hi; }
                else if (pp == 3) { d0[k] += g[6]*lo;
                                    d1[k] += g[2]*lo + g[3]*hi; }
                else if (pp == 4) { d1[k] += g[4]*lo + g[5]*hi; }
                else              { d1[k] += g[6]*lo; }
            }
        }
        if (q == 27) { d0[6]=0.f; d0[7]=0.f; d1[6]=0.f; d1[7]=0.f; }

        float n5a = __shfl_up_sync(0xffffffffu, d0[5], 1);
        float n6a = __shfl_up_sync(0xffffffffu, d0[6], 1);
        float n7a = __shfl_up_sync(0xffffffffu, d0[7], 1);
        float n5b = __shfl_up_sync(0xffffffffu, d1[5], 1);
        float n6b = __shfl_up_sync(0xffffffffu, d1[6], 1);
        float n7b = __shfl_up_sync(0xffffffffu, d1[7], 1);
        if (q == 0) { n5a=0.f; n6a=0.f; n7a=0.f; n5b=0.f; n6b=0.f; n7b=0.f; }

        float oe0 = g[0]*n5a + g[1]*n6a + g[2]*n7a
                  + g[3]*d0[0] + g[4]*d0[1] + g[5]*d0[2] + g[6]*d0[3];
        float oo0 = g[0]*d0[1] + g[1]*d0[2] + g[2]*d0[3] + g[3]*d0[4]
                  + g[4]*d0[5] + g[5]*d0[6] + g[6]*d0[7];
        float oe1 = g[0]*n5b + g[1]*n6b + g[2]*n7b
                  + g[3]*d1[0] + g[4]*d1[1] + g[5]*d1[2] + g[6]*d1[3];
        float oo1 = g[0]*d1[1] + g[1]*d1[2] + g[2]*d1[3] + g[3]*d1[4]
                  + g[4]*d1[5] + g[5]*d1[6] + g[6]*d1[7];

        if (lane < 28) {
            float* ob = out + (size_t)(nc0 + img)*(HOUT*WOUT)
                            + (size_t)(i0 + 2*lp)*WOUT + 2*q;
            *reinterpret_cast<float2*>(ob)        = make_float2(oe0, oo0);
            *reinterpret_cast<float2*>(ob + WOUT) = make_float2(oe1, oo1);
        }
    }
}

extern "C" void kernel_launch(void* const* d_in, const int* in_sizes, int n_in,
                              void* d_out, int out_size)
{
    const float* x     = (const float*)d_in[0];   // (32,64,112,112)
    const float* fpre  = (const float*)d_in[1];   // (7,)
    const float* fpost = (const float*)d_in[2];   // (7,)
    float* out = (float*)d_out;                   // (32,64,56,56)

    const size_t smem_bytes = SMEM_WORDS * sizeof(unsigned); // 33408
    cudaFuncSetAttribute(aamaxpool_fused_kernel,
                         cudaFuncAttributeMaxDynamicSharedMemorySize,
                         (int)smem_bytes);

    dim3 grid(HOUT / TI, 32 * 64 / 2);   // 7 strips x 1024 image-pairs
    aamaxpool_fused_kernel<<<grid, NTHREADS, smem_bytes>>>(x, fpre, fpost, out);
}

// round 13
// speedup vs baseline: 1.0004x; 1.0004x over previous
#include <cuda_runtime.h>
#include <cuda_fp16.h>

// Fused AA max-pool: up2+FIR7 -> maxpool5x5 s1 -> FIR7+down4.
// One CTA = TWO (n,c) images x 8 output rows, 256 threads.
// R10 pipeline (half2 row-pair packing, LDS-based stages) with sA2 PHASED:
// a 10-pack buffer filled/consumed twice, shrinking smem 52->42.7 KB so
// 5 CTAs/SM fit. Instruction stream otherwise identical to R10.

#define WIN  112
#define TI   8
#define WAS  116                 // sA2: col c at word c+1 (c in [-1,113])
#define PHP  10                  // packs per phase (2 phases x 10 = 20)
#define A_WORDS (PHP*WAS)        // 1160 per image
#define WMS2 232                 // sM row stride (words); col v at word v+4
#define PM   18                  // M packs (rows 0..35)
#define M_WORDS (PM*WMS2)        // 4176
#define HOUT 56
#define WOUT 56
#define NTHREADS 256

#define OFF_M 0                          // 2 imgs x 4176 words
#define OFF_A (2*M_WORDS)                // 2 imgs x 1160 words
#define SMEM_WORDS (OFF_A + 2*A_WORDS)   // 10672 words = 42688 B -> 5 CTAs/SM

__device__ __forceinline__ int swz(int c) { return c ^ (((c >> 5) & 1) << 2); }

__device__ __forceinline__ __half2 h2shift(__half2 a, __half2 b) {
    unsigned r = __byte_perm(*(unsigned*)&a, *(unsigned*)&b, 0x5432);
    return *(__half2*)&r;
}

// ---- phased stages 1+2, templated on EDGE handling ----
template<bool EDGE>
__device__ __forceinline__ void stage12(
    unsigned* __restrict__ sA2, unsigned* __restrict__ sMh,
    const float* __restrict__ x, int nc0, int t,
    int in_row0, int u0,
    float f0, float f1, float f2, float f3, float f4, float f5, float f6,
    __half2 f0h, __half2 f1h, __half2 f2h, __half2 f3h,
    __half2 f4h, __half2 f5h, __half2 f6h)
{
    const unsigned NEG2U = 0xFC00FC00u;
    const __half2 NEG2 = *(const __half2*)&NEG2U;

    const bool act = (t < 224);
    const int img = act ? (t / 112) : 0;
    const int w   = act ? (t - 112*img) : 0;

    const float* col = x + (size_t)(nc0 + img) * (WIN*WIN) + w;
    unsigned* sAc = sA2 + img*A_WORDS + (w + 1);
    const unsigned* ap = sA2 + img*A_WORDS + w;          // words = cols w-1..w+2
    unsigned* mrow = sMh + img*M_WORDS + swz(2*w + 4);   // col pair (2w,2w+1)

    int jlo = 0, jhi = 20;
    if (EDGE) {
        int v = (0 - u0) > 0 ? (0 - u0) : 0;
        jlo = v >> 1;
        jhi = (224 - u0) >> 1; if (jhi > 20) jhi = 20;
    }

    float x0 = 0.f, x1 = 0.f, x2 = 0.f;
    if (act) {
        if (EDGE) {
            int r;
            r = in_row0;     x0 = (r>=0 && r<WIN) ? col[r*WIN] : 0.f;
            r = in_row0 + 1; x1 = (r>=0 && r<WIN) ? col[r*WIN] : 0.f;
            r = in_row0 + 2; x2 = (r>=0 && r<WIN) ? col[r*WIN] : 0.f;
        } else {
            x0 = col[in_row0*WIN];
            x1 = col[(in_row0+1)*WIN];
            x2 = col[(in_row0+2)*WIN];
        }
    }

    __half2 PeP = NEG2, PoP = NEG2, AeP = NEG2, AoP = NEG2;

#pragma unroll
    for (int ph = 0; ph < 2; ph++) {
        // ---- fill: vertical up-2 FIR for packs 10ph .. 10ph+9 ----
        if (act) {
#pragma unroll
            for (int qq = 0; qq < PHP; qq++) {
                int r = in_row0 + 10*ph + qq + 3;
                float x3;
                if (EDGE) x3 = (r>=0 && r<WIN) ? col[r*WIN] : 0.f;
                else      x3 = col[r*WIN];
                float ae = f1*x0 + f3*x1 + f5*x2;           // A row 2(10ph+qq)
                float ao = f0*x0 + f2*x1 + f4*x2 + f6*x3;   // A row 2(10ph+qq)+1
                __half2 h = __floats2half2_rn(ae, ao);
                sAc[qq*WAS] = *(unsigned*)&h;
                x0 = x1; x1 = x2; x2 = x3;
            }
            // sA2 halo zeros: words {0,113,114} x 10 packs x 2 imgs = 60
            for (int idx = t; idx < 60; idx += 224) {
                int im = idx / 30, rem = idx - 30*im;
                int q = rem / 3, k = rem - 3*q;
                sA2[im*A_WORDS + q*WAS + (k == 0 ? 0 : 112 + k)] = 0u;
            }
        }
        __syncthreads();

        // ---- consume: HFMA2 horizontal up-FIR + packed rolling 5-row max ----
        if (act) {
#pragma unroll
            for (int jj = 0; jj < PHP; jj++) {
                const int j = 10*ph + jj;
                const unsigned* a = ap + jj*WAS;
                __half2 a0=*(__half2*)&a[0], a1=*(__half2*)&a[1],
                        a2=*(__half2*)&a[2], a3=*(__half2*)&a[3];
                __half2 be = __hfma2(f5h,a2, __hfma2(f3h,a1, __hmul2(f1h,a0)));
                __half2 bo = __hfma2(f6h,a3, __hfma2(f4h,a2,
                              __hfma2(f2h,a1, __hmul2(f0h,a0))));
                __half2 Pe, Po;
                if (EDGE) {
                    bool valid = (j >= jlo) && (j < jhi);
                    Pe = valid ? be : NEG2;
                    Po = valid ? bo : NEG2;
                } else { Pe = be; Po = bo; }
                __half2 Ae = __hmax2(PeP, h2shift(PeP, Pe));
                __half2 Ao = __hmax2(PoP, h2shift(PoP, Po));
                if (j >= 2) {
                    __half2 Me = __hmax2(AeP, __hmax2(Ae, Pe));
                    __half2 Mo = __hmax2(AoP, __hmax2(Ao, Po));
                    uint2 mm = make_uint2(*(unsigned*)&Me, *(unsigned*)&Mo);
                    *reinterpret_cast<uint2*>(mrow + (j - 2)*WMS2) = mm;
                }
                AeP = Ae; AoP = Ao; PeP = Pe; PoP = Po;
            }
        }
        __syncthreads();   // WAR: next fill overwrites buffer / final pre-stage3
    }
}

__global__ void __launch_bounds__(NTHREADS, 5)
aamaxpool_fused_kernel(const float* __restrict__ x,
                       const float* __restrict__ fpre,
                       const float* __restrict__ fpost,
                       float* __restrict__ out)
{
    extern __shared__ unsigned smu[];
    unsigned* sMh = smu + OFF_M;
    unsigned* sA2 = smu + OFF_A;

    const int t  = threadIdx.x;
    const int i0 = blockIdx.x * TI;
    const int nc0 = 2 * blockIdx.y;
    const int in_row0 = 2*i0 - 3;
    const int u0 = 4*i0 - 4;
    const int r0 = 4*i0 - 3;
    const unsigned NEG2U = 0xFC00FC00u;
    const bool edge = (blockIdx.x == 0) | (blockIdx.x == 6);

    const float f0=__ldg(fpre+0), f1=__ldg(fpre+1), f2=__ldg(fpre+2),
                f3=__ldg(fpre+3), f4=__ldg(fpre+4), f5=__ldg(fpre+5),
                f6=__ldg(fpre+6);
    const __half2 f0h=__float2half2_rn(f0), f1h=__float2half2_rn(f1),
                  f2h=__float2half2_rn(f2), f3h=__float2half2_rn(f3),
                  f4h=__float2half2_rn(f4), f5h=__float2half2_rn(f5),
                  f6h=__float2half2_rn(f6);
    float g[7];
#pragma unroll
    for (int i = 0; i < 7; i++) g[i] = __ldg(fpost + i);

    // ---- sM halo pads: colwords {0..3, 228..231} x 18 packs x 2 imgs ----
    for (int idx = t; idx < 2*PM*8; idx += NTHREADS) {
        int im = idx / (PM*8), rem = idx - im*(PM*8);
        int jm = rem >> 3, k = rem & 7;
        int c = (k < 4) ? k : 224 + k;
        sMh[im*M_WORDS + jm*WMS2 + swz(c)] = NEG2U;
    }

    if (edge) {
        stage12<true >(sA2, sMh, x, nc0, t, in_row0, u0,
                       f0,f1,f2,f3,f4,f5,f6, f0h,f1h,f2h,f3h,f4h,f5h,f6h);
        // edge fix-up: zero M rows with rg outside [0,222) (FIR zero-pad)
        int btop = (-r0 > 0) ? -r0 : 0;
        int lc0 = 222 - r0; if (lc0 > 35) lc0 = 35;
        if (btop > 0 || lc0 < 35) {
            for (int idx = t; idx < 2*WMS2; idx += NTHREADS) {
                int im = idx / WMS2, c = idx - WMS2*im;
                unsigned* Mi = sMh + im*M_WORDS;
                int cw = swz(c);
                for (int lc = 0; lc < btop; lc++)
                    ((unsigned short*)(Mi + (lc>>1)*WMS2 + cw))[lc & 1] = 0;
                for (int lc = lc0; lc < 35; lc++)
                    ((unsigned short*)(Mi + (lc>>1)*WMS2 + cw))[lc & 1] = 0;
            }
            __syncthreads();
        }
    } else {
        stage12<false>(sA2, sMh, x, nc0, t, in_row0, u0,
                       f0,f1,f2,f3,f4,f5,f6, f0h,f1h,f2h,f3h,f4h,f5h,f6h);
    }

    // ---- stage 3: packed 5-col max + vertical FIR + shfl horizontal FIR ----
    {
        const int wid = t >> 5, lane = t & 31;
        const int img = wid >> 2;                  // warps 0-3 img0, 4-7 img1
        const int lp  = wid & 3;                   // output rows 2lp, 2lp+1
        const int q   = (lane < 28) ? lane : 27;
        const unsigned* Mi = sMh + img*M_WORDS;
        float d0[8] = {0,0,0,0,0,0,0,0};
        float d1[8] = {0,0,0,0,0,0,0,0};
#pragma unroll
        for (int pp = 0; pp < 6; pp++) {
            const int pg = 4*lp + pp;
            const unsigned* base = Mi + pg*WMS2;
            unsigned Cw[16];
#pragma unroll
            for (int gi = 0; gi < 4; gi++) {
                uint4 v = *reinterpret_cast<const uint4*>(base + swz(8*q + 4*gi));
                Cw[4*gi+0] = v.x; Cw[4*gi+1] = v.y; Cw[4*gi+2] = v.z; Cw[4*gi+3] = v.w;
            }
            __half2 C[16];
#pragma unroll
            for (int i = 0; i < 16; i++) C[i] = *(__half2*)&Cw[i];
            __half2 p[10];                          // p[i-3] = max(C[i],C[i+1])
#pragma unroll
            for (int i = 0; i < 10; i++) p[i] = __hmax2(C[i+3], C[i+4]);
#pragma unroll
            for (int k = 0; k < 8; k++) {
                __half2 wmx = __hmax2(p[k], __hmax2(p[k+2], C[k+7]));
                float lo = __low2float(wmx);
                float hi = __high2float(wmx);
                if (pp == 0)      { d0[k] += g[0]*lo + g[1]*hi; }
                else if (pp == 1) { d0[k] += g[2]*lo + g[3]*hi; }
                else if (pp == 2) { d0[k] += g[4]*lo + g[5]*hi;
                                    d1[k] += g[0]*lo + g[1]*hi; }
                else if (pp == 3) { d0[k] += g[6]*lo;
                                    d1[k] += g[2]*lo + g[3]*hi; }
                else if (pp == 4) { d1[k] += g[4]*lo + g[5]*hi; }
                else              { d1[k] += g[6]*lo; }
            }
        }
        if (q == 27) { d0[6]=0.f; d0[7]=0.f; d1[6]=0.f; d1[7]=0.f; }

        float n5a = __shfl_up_sync(0xffffffffu, d0[5], 1);
        float n6a = __shfl_up_sync(0xffffffffu, d0[6], 1);
        float n7a = __shfl_up_sync(0xffffffffu, d0[7], 1);
        float n5b = __shfl_up_sync(0xffffffffu, d1[5], 1);
        float n6b = __shfl_up_sync(0xffffffffu, d1[6], 1);
        float n7b = __shfl_up_sync(0xffffffffu, d1[7], 1);
        if (q == 0) { n5a=0.f; n6a=0.f; n7a=0.f; n5b=0.f; n6b=0.f; n7b=0.f; }

        float oe0 = g[0]*n5a + g[1]*n6a + g[2]*n7a
                  + g[3]*d0[0] + g[4]*d0[1] + g[5]*d0[2] + g[6]*d0[3];
        float oo0 = g[0]*d0[1] + g[1]*d0[2] + g[2]*d0[3] + g[3]*d0[4]
                  + g[4]*d0[5] + g[5]*d0[6] + g[6]*d0[7];
        float oe1 = g[0]*n5b + g[1]*n6b + g[2]*n7b
                  + g[3]*d1[0] + g[4]*d1[1] + g[5]*d1[2] + g[6]*d1[3];
        float oo1 = g[0]*d1[1] + g[1]*d1[2] + g[2]*d1[3] + g[3]*d1[4]
                  + g[4]*d1[5] + g[5]*d1[6] + g[6]*d1[7];

        if (lane < 28) {
            float* ob = out + (size_t)(nc0 + img)*(HOUT*WOUT)
                            + (size_t)(i0 + 2*lp)*WOUT + 2*q;
            *reinterpret_cast<float2*>(ob)        = make_float2(oe0, oo0);
            *reinterpret_cast<float2*>(ob + WOUT) = make_float2(oe1, oo1);
        }
    }
}

extern "C" void kernel_launch(void* const* d_in, const int* in_sizes, int n_in,
                              void* d_out, int out_size)
{
    const float* x     = (const float*)d_in[0];   // (32,64,112,112)
    const float* fpre  = (const float*)d_in[1];   // (7,)
    const float* fpost = (const float*)d_in[2];   // (7,)
    float* out = (float*)d_out;                   // (32,64,56,56)

    const size_t smem_bytes = SMEM_WORDS * sizeof(unsigned); // 42688
    cudaFuncSetAttribute(aamaxpool_fused_kernel,
                         cudaFuncAttributeMaxDynamicSharedMemorySize,
                         (int)smem_bytes);

    dim3 grid(HOUT / TI, 32 * 64 / 2);   // 7 strips x 1024 image-pairs
    aamaxpool_fused_kernel<<<grid, NTHREADS, smem_bytes>>>(x, fpre, fpost, out);
}

// round 16
// speedup vs baseline: 1.0234x; 1.0231x over previous
#include <cuda_runtime.h>
#include <cuda_fp16.h>

// Fused AA max-pool: up2+FIR7 -> maxpool5x5 s1 -> FIR7+down4.
// One CTA = TWO (n,c) images x 8 output rows, 256 threads.
// R10 pipeline (half2 row-pair packing, LDS-based stages, edge/interior
// template split). Delta vs R10: all smem init loops (sM -inf pads, sA2
// halo zeros) moved onto warp 7, which is otherwise idle during stages
// 1-2 -- they now overlap stage 1 for free. Hot loops identical to R10.

#define WIN  112
#define TI   8
#define WAS  116                 // sA2: col c at word c+1 (c in [-1,113])
#define PA   20                  // A packs (rows 0..39)
#define A_WORDS (PA*WAS)         // 2320
#define WMS2 232                 // sM row stride (words); col v at word v+4
#define PM   18                  // M packs (rows 0..35)
#define M_WORDS (PM*WMS2)        // 4176
#define HOUT 56
#define WOUT 56
#define NTHREADS 256

#define OFF_M 0                          // 2 imgs x 4176 words
#define OFF_A (2*M_WORDS)                // 2 imgs x 2320 words
#define SMEM_WORDS (OFF_A + 2*A_WORDS)   // 12992 words = 51968 B -> 4 CTAs/SM

__device__ __forceinline__ int swz(int c) { return c ^ (((c >> 5) & 1) << 2); }

__device__ __forceinline__ __half2 h2shift(__half2 a, __half2 b) {
    unsigned r = __byte_perm(*(unsigned*)&a, *(unsigned*)&b, 0x5432);
    return *(__half2*)&r;
}

// ---- stages 1+2, templated on EDGE handling; warp 7 does smem inits ----
template<bool EDGE>
__device__ __forceinline__ void stage12(
    unsigned* __restrict__ sA2, unsigned* __restrict__ sMh,
    const float* __restrict__ x, int nc0, int t,
    int in_row0, int u0,
    float f0, float f1, float f2, float f3, float f4, float f5, float f6,
    __half2 f0h, __half2 f1h, __half2 f2h, __half2 f3h,
    __half2 f4h, __half2 f5h, __half2 f6h)
{
    const unsigned NEG2U = 0xFC00FC00u;
    const __half2 NEG2 = *(const __half2*)&NEG2U;

    if (t < 224) {
        const int img = t / 112;
        const int w   = t - 112*img;

        // ---- stage 1: vertical up-2 FIR -> half2 pack -> sA2 ----
        const float* col = x + (size_t)(nc0 + img) * (WIN*WIN) + w;
        unsigned* sAc = sA2 + img*A_WORDS + (w + 1);
        float x0, x1, x2;
        if (EDGE) {
            int r;
            r = in_row0;     x0 = (r>=0 && r<WIN) ? col[r*WIN] : 0.f;
            r = in_row0 + 1; x1 = (r>=0 && r<WIN) ? col[r*WIN] : 0.f;
            r = in_row0 + 2; x2 = (r>=0 && r<WIN) ? col[r*WIN] : 0.f;
        } else {
            x0 = col[in_row0*WIN];
            x1 = col[(in_row0+1)*WIN];
            x2 = col[(in_row0+2)*WIN];
        }
#pragma unroll
        for (int q = 0; q < 20; q++) {
            int r = in_row0 + q + 3;
            float x3;
            if (EDGE) x3 = (r>=0 && r<WIN) ? col[r*WIN] : 0.f;
            else      x3 = col[r*WIN];
            float ae = f1*x0 + f3*x1 + f5*x2;           // A row 2q
            float ao = f0*x0 + f2*x1 + f4*x2 + f6*x3;   // A row 2q+1
            __half2 h = __floats2half2_rn(ae, ao);
            sAc[q*WAS] = *(unsigned*)&h;
            x0 = x1; x1 = x2; x2 = x3;
        }
    } else {
        // ---- warp 7 (idle otherwise): smem init, overlapped with stage 1 ----
        const int lane = t - 224;
        // sM -inf pads: colwords {0..3, 228..231} x 18 packs x 2 imgs = 288
        for (int idx = lane; idx < 2*PM*8; idx += 32) {
            int im = idx / (PM*8), rem = idx - im*(PM*8);
            int jm = rem >> 3, k = rem & 7;
            int c = (k < 4) ? k : 224 + k;
            sMh[im*M_WORDS + jm*WMS2 + swz(c)] = NEG2U;
        }
        // sA2 halo zeros: words {0,113,114} x 20 packs x 2 imgs = 120
        for (int idx = lane; idx < 120; idx += 32) {
            int im = idx / 60, rem = idx - 60*im;
            int q = rem / 3, k = rem - 3*q;
            sA2[im*A_WORDS + q*WAS + (k == 0 ? 0 : 112 + k)] = 0u;
        }
    }
    __syncthreads();

    // ---- stage 2: HFMA2 horizontal up-FIR + packed rolling 5-row max ----
    if (t < 224) {
        const int img = t / 112;
        const int w   = t - 112*img;
        const unsigned* ap = sA2 + img*A_WORDS + w;   // words = cols w-1..w+2
        unsigned* mrow = sMh + img*M_WORDS + swz(2*w + 4);
        int jlo = 0, jhi = 20;
        if (EDGE) {
            int v = (0 - u0) > 0 ? (0 - u0) : 0;
            jlo = v >> 1;
            jhi = (224 - u0) >> 1; if (jhi > 20) jhi = 20;
        }
        __half2 PeP = NEG2, PoP = NEG2, AeP = NEG2, AoP = NEG2;
#pragma unroll
        for (int j = 0; j < 20; j++) {
            const unsigned* a = ap + j*WAS;
            __half2 a0=*(__half2*)&a[0], a1=*(__half2*)&a[1],
                    a2=*(__half2*)&a[2], a3=*(__half2*)&a[3];
            __half2 be = __hfma2(f5h,a2, __hfma2(f3h,a1, __hmul2(f1h,a0)));
            __half2 bo = __hfma2(f6h,a3, __hfma2(f4h,a2,
                          __hfma2(f2h,a1, __hmul2(f0h,a0))));
            __half2 Pe, Po;
            if (EDGE) {
                bool valid = (j >= jlo) && (j < jhi);
                Pe = valid ? be : NEG2;
                Po = valid ? bo : NEG2;
            } else { Pe = be; Po = bo; }
            __half2 Ae = __hmax2(PeP, h2shift(PeP, Pe));
            __half2 Ao = __hmax2(PoP, h2shift(PoP, Po));
            if (j >= 2) {
                __half2 Me = __hmax2(AeP, __hmax2(Ae, Pe));
                __half2 Mo = __hmax2(AoP, __hmax2(Ao, Po));
                uint2 mm = make_uint2(*(unsigned*)&Me, *(unsigned*)&Mo);
                *reinterpret_cast<uint2*>(mrow + (j - 2)*WMS2) = mm;
            }
            AeP = Ae; AoP = Ao; PeP = Pe; PoP = Po;
        }
    }
    __syncthreads();
}

__global__ void __launch_bounds__(NTHREADS, 4)
aamaxpool_fused_kernel(const float* __restrict__ x,
                       const float* __restrict__ fpre,
                       const float* __restrict__ fpost,
                       float* __restrict__ out)
{
    extern __shared__ unsigned smu[];
    unsigned* sMh = smu + OFF_M;
    unsigned* sA2 = smu + OFF_A;

    const int t  = threadIdx.x;
    const int i0 = blockIdx.x * TI;
    const int nc0 = 2 * blockIdx.y;
    const int in_row0 = 2*i0 - 3;
    const int u0 = 4*i0 - 4;
    const int r0 = 4*i0 - 3;
    const bool edge = (blockIdx.x == 0) | (blockIdx.x == 6);

    const float f0=__ldg(fpre+0), f1=__ldg(fpre+1), f2=__ldg(fpre+2),
                f3=__ldg(fpre+3), f4=__ldg(fpre+4), f5=__ldg(fpre+5),
                f6=__ldg(fpre+6);
    const __half2 f0h=__float2half2_rn(f0), f1h=__float2half2_rn(f1),
                  f2h=__float2half2_rn(f2), f3h=__float2half2_rn(f3),
                  f4h=__float2half2_rn(f4), f5h=__float2half2_rn(f5),
                  f6h=__float2half2_rn(f6);

    if (edge) {
        stage12<true >(sA2, sMh, x, nc0, t, in_row0, u0,
                       f0,f1,f2,f3,f4,f5,f6, f0h,f1h,f2h,f3h,f4h,f5h,f6h);
        // edge fix-up: zero M rows with rg outside [0,222) (FIR zero-pad)
        int btop = (-r0 > 0) ? -r0 : 0;
        int lc0 = 222 - r0; if (lc0 > 35) lc0 = 35;
        if (btop > 0 || lc0 < 35) {
            for (int idx = t; idx < 2*WMS2; idx += NTHREADS) {
                int im = idx / WMS2, c = idx - WMS2*im;
                unsigned* Mi = sMh + im*M_WORDS;
                int cw = swz(c);
                for (int lc = 0; lc < btop; lc++)
                    ((unsigned short*)(Mi + (lc>>1)*WMS2 + cw))[lc & 1] = 0;
                for (int lc = lc0; lc < 35; lc++)
                    ((unsigned short*)(Mi + (lc>>1)*WMS2 + cw))[lc & 1] = 0;
            }
            __syncthreads();
        }
    } else {
        stage12<false>(sA2, sMh, x, nc0, t, in_row0, u0,
                       f0,f1,f2,f3,f4,f5,f6, f0h,f1h,f2h,f3h,f4h,f5h,f6h);
    }

    // ---- stage 3: packed 5-col max + vertical FIR + shfl horizontal FIR ----
    {
        float g[7];
#pragma unroll
        for (int i = 0; i < 7; i++) g[i] = __ldg(fpost + i);

        const int wid = t >> 5, lane = t & 31;
        const int img = wid >> 2;                  // warps 0-3 img0, 4-7 img1
        const int lp  = wid & 3;                   // output rows 2lp, 2lp+1
        const int q   = (lane < 28) ? lane : 27;
        const unsigned* Mi = sMh + img*M_WORDS;
        float d0[8] = {0,0,0,0,0,0,0,0};
        float d1[8] = {0,0,0,0,0,0,0,0};
#pragma unroll
        for (int pp = 0; pp < 6; pp++) {
            const int pg = 4*lp + pp;
            const unsigned* base = Mi + pg*WMS2;
            unsigned Cw[16];
#pragma unroll
            for (int gi = 0; gi < 4; gi++) {
                uint4 v = *reinterpret_cast<const uint4*>(base + swz(8*q + 4*gi));
                Cw[4*gi+0] = v.x; Cw[4*gi+1] = v.y; Cw[4*gi+2] = v.z; Cw[4*gi+3] = v.w;
            }
            __half2 C[16];
#pragma unroll
            for (int i = 0; i < 16; i++) C[i] = *(__half2*)&Cw[i];
            __half2 p[10];                          // p[i-3] = max(C[i],C[i+1])
#pragma unroll
            for (int i = 0; i < 10; i++) p[i] = __hmax2(C[i+3], C[i+4]);
#pragma unroll
            for (int k = 0; k < 8; k++) {
                __half2 wmx = __hmax2(p[k], __hmax2(p[k+2], C[k+7]));
                float lo = __low2float(wmx);
                float hi = __high2float(wmx);
                if (pp == 0)      { d0[k] += g[0]*lo + g[1]*hi; }
                else if (pp == 1) { d0[k] += g[2]*lo + g[3]*hi; }
                else if (pp == 2) { d0[k] += g[4]*lo + g[5]*hi;
                                    d1[k] += g[0]*lo + g[1]*hi; }
                else if (pp == 3) { d0[k] += g[6]*lo;
                                    d1[k] += g[2]*lo + g[3]*hi; }
                else if (pp == 4) { d1[k] += g[4]*lo + g[5]*hi; }
                else              { d1[k] += g[6]*lo; }
            }
        }
        if (q == 27) { d0[6]=0.f; d0[7]=0.f; d1[6]=0.f; d1[7]=0.f; }

        float n5a = __shfl_up_sync(0xffffffffu, d0[5], 1);
        float n6a = __shfl_up_sync(0xffffffffu, d0[6], 1);
        float n7a = __shfl_up_sync(0xffffffffu, d0[7], 1);
        float n5b = __shfl_up_sync(0xffffffffu, d1[5], 1);
        float n6b = __shfl_up_sync(0xffffffffu, d1[6], 1);
        float n7b = __shfl_up_sync(0xffffffffu, d1[7], 1);
        if (q == 0) { n5a=0.f; n6a=0.f; n7a=0.f; n5b=0.f; n6b=0.f; n7b=0.f; }

        float oe0 = g[0]*n5a + g[1]*n6a + g[2]*n7a
                  + g[3]*d0[0] + g[4]*d0[1] + g[5]*d0[2] + g[6]*d0[3];
        float oo0 = g[0]*d0[1] + g[1]*d0[2] + g[2]*d0[3] + g[3]*d0[4]
                  + g[4]*d0[5] + g[5]*d0[6] + g[6]*d0[7];
        float oe1 = g[0]*n5b + g[1]*n6b + g[2]*n7b
                  + g[3]*d1[0] + g[4]*d1[1] + g[5]*d1[2] + g[6]*d1[3];
        float oo1 = g[0]*d1[1] + g[1]*d1[2] + g[2]*d1[3] + g[3]*d1[4]
                  + g[4]*d1[5] + g[5]*d1[6] + g[6]*d1[7];

        if (lane < 28) {
            float* ob = out + (size_t)(nc0 + img)*(HOUT*WOUT)
                            + (size_t)(i0 + 2*lp)*WOUT + 2*q;
            *reinterpret_cast<float2*>(ob)        = make_float2(oe0, oo0);
            *reinterpret_cast<float2*>(ob + WOUT) = make_float2(oe1, oo1);
        }
    }
}

extern "C" void kernel_launch(void* const* d_in, const int* in_sizes, int n_in,
                              void* d_out, int out_size)
{
    const float* x     = (const float*)d_in[0];   // (32,64,112,112)
    const float* fpre  = (const float*)d_in[1];   // (7,)
    const float* fpost = (const float*)d_in[2];   // (7,)
    float* out = (float*)d_out;                   // (32,64,56,56)

    const size_t smem_bytes = SMEM_WORDS * sizeof(unsigned); // 51968
    cudaFuncSetAttribute(aamaxpool_fused_kernel,
                         cudaFuncAttributeMaxDynamicSharedMemorySize,
                         (int)smem_bytes);

    dim3 grid(HOUT / TI, 32 * 64 / 2);   // 7 strips x 1024 image-pairs
    aamaxpool_fused_kernel<<<grid, NTHREADS, smem_bytes>>>(x, fpre, fpost, out);
}

// round 17
// speedup vs baseline: 1.0512x; 1.0271x over previous
#include <cuda_runtime.h>
#include <cuda_fp16.h>
#include <cstdint>

// Fused AA max-pool: up2+FIR7 -> maxpool5x5 s1 -> FIR7+down4.
// One CTA = TWO (n,c) images x 8 output rows, 256 threads.
// R10 pipeline (half2 row-pair packing, LDS-based stages, edge/interior
// template split). Delta vs R10: stage-1 vertical polyphase FIR computed
// with packed fp32x2 (mul/fma.rn.f32x2) -- 1 MUL2+3 FMA2+1 MOV replaces
// 7 FFMA per pack. Identical rounding; everything else byte-identical.

#define WIN  112
#define TI   8
#define WAS  116                 // sA2: col c at word c+1 (c in [-1,113])
#define PA   20                  // A packs (rows 0..39)
#define A_WORDS (PA*WAS)         // 2320
#define WMS2 232                 // sM row stride (words); col v at word v+4
#define PM   18                  // M packs (rows 0..35)
#define M_WORDS (PM*WMS2)        // 4176
#define HOUT 56
#define WOUT 56
#define NTHREADS 256

#define OFF_M 0                          // 2 imgs x 4176 words
#define OFF_A (2*M_WORDS)                // 2 imgs x 2320 words
#define SMEM_WORDS (OFF_A + 2*A_WORDS)   // 12992 words = 51968 B -> 4 CTAs/SM

__device__ __forceinline__ int swz(int c) { return c ^ (((c >> 5) & 1) << 2); }

__device__ __forceinline__ __half2 h2shift(__half2 a, __half2 b) {
    unsigned r = __byte_perm(*(unsigned*)&a, *(unsigned*)&b, 0x5432);
    return *(__half2*)&r;
}

// ---- packed fp32x2 helpers (sm_100+) ----
__device__ __forceinline__ uint64_t f2pack(float lo, float hi) {
    uint64_t r;
    asm("mov.b64 %0, {%1, %2};" : "=l"(r) : "f"(lo), "f"(hi));
    return r;
}
__device__ __forceinline__ uint64_t f2mul(uint64_t a, uint64_t b) {
    uint64_t d;
    asm("mul.rn.f32x2 %0, %1, %2;" : "=l"(d) : "l"(a), "l"(b));
    return d;
}
__device__ __forceinline__ uint64_t f2fma(uint64_t a, uint64_t b, uint64_t c) {
    uint64_t d;
    asm("fma.rn.f32x2 %0, %1, %2, %3;" : "=l"(d) : "l"(a), "l"(b), "l"(c));
    return d;
}
__device__ __forceinline__ void f2unpack(uint64_t v, float& lo, float& hi) {
    asm("mov.b64 {%0, %1}, %2;" : "=f"(lo), "=f"(hi) : "l"(v));
}

// ---- stages 1+2, templated on EDGE handling ----
template<bool EDGE>
__device__ __forceinline__ void stage12(
    unsigned* __restrict__ sA2, unsigned* __restrict__ sMh,
    const float* __restrict__ x, int nc0, int t,
    int in_row0, int u0,
    float f0, float f1, float f2, float f3, float f4, float f5, float f6,
    __half2 f0h, __half2 f1h, __half2 f2h, __half2 f3h,
    __half2 f4h, __half2 f5h, __half2 f6h)
{
    const unsigned NEG2U = 0xFC00FC00u;
    const __half2 NEG2 = *(const __half2*)&NEG2U;

    if (t < 224) {
        const int img = t / 112;
        const int w   = t - 112*img;

        // ---- stage 1: vertical up-2 FIR (fp32x2 lanes: lo=even, hi=odd) ----
        {
            const float* col = x + (size_t)(nc0 + img) * (WIN*WIN) + w;
            unsigned* sAc = sA2 + img*A_WORDS + (w + 1);
            const uint64_t CP0 = f2pack(f1, f0);
            const uint64_t CP1 = f2pack(f3, f2);
            const uint64_t CP2 = f2pack(f5, f4);
            const uint64_t CP3 = f2pack(0.f, f6);
            float x0, x1, x2;
            if (EDGE) {
                int r;
                r = in_row0;     x0 = (r>=0 && r<WIN) ? col[r*WIN] : 0.f;
                r = in_row0 + 1; x1 = (r>=0 && r<WIN) ? col[r*WIN] : 0.f;
                r = in_row0 + 2; x2 = (r>=0 && r<WIN) ? col[r*WIN] : 0.f;
            } else {
                x0 = col[in_row0*WIN];
                x1 = col[(in_row0+1)*WIN];
                x2 = col[(in_row0+2)*WIN];
            }
            uint64_t X0 = f2pack(x0, x0);
            uint64_t X1 = f2pack(x1, x1);
            uint64_t X2 = f2pack(x2, x2);
#pragma unroll
            for (int q = 0; q < 20; q++) {
                int r = in_row0 + q + 3;
                float x3;
                if (EDGE) x3 = (r>=0 && r<WIN) ? col[r*WIN] : 0.f;
                else      x3 = col[r*WIN];
                uint64_t X3 = f2pack(x3, x3);
                uint64_t acc = f2mul(CP0, X0);        // (f1*x0, f0*x0)
                acc = f2fma(CP1, X1, acc);            // +(f3*x1, f2*x1)
                acc = f2fma(CP2, X2, acc);            // +(f5*x2, f4*x2)
                acc = f2fma(CP3, X3, acc);            // +(0,     f6*x3)
                float ae, ao;
                f2unpack(acc, ae, ao);                // free at SASS level
                __half2 h = __floats2half2_rn(ae, ao);
                sAc[q*WAS] = *(unsigned*)&h;
                X0 = X1; X1 = X2; X2 = X3;
            }
        }
        // sA2 halo zeros: words {0,113,114} x 20 packs x 2 imgs = 120
        for (int idx = t; idx < 120; idx += 224) {
            int im = idx / 60, rem = idx - 60*im;
            int q = rem / 3, k = rem - 3*q;
            sA2[im*A_WORDS + q*WAS + (k == 0 ? 0 : 112 + k)] = 0u;
        }
    }
    __syncthreads();

    // ---- stage 2: HFMA2 horizontal up-FIR + packed rolling 5-row max ----
    if (t < 224) {
        const int img = t / 112;
        const int w   = t - 112*img;
        const unsigned* ap = sA2 + img*A_WORDS + w;   // words = cols w-1..w+2
        unsigned* mrow = sMh + img*M_WORDS + swz(2*w + 4);
        int jlo = 0, jhi = 20;
        if (EDGE) {
            int v = (0 - u0) > 0 ? (0 - u0) : 0;
            jlo = v >> 1;
            jhi = (224 - u0) >> 1; if (jhi > 20) jhi = 20;
        }
        __half2 PeP = NEG2, PoP = NEG2, AeP = NEG2, AoP = NEG2;
#pragma unroll
        for (int j = 0; j < 20; j++) {
            const unsigned* a = ap + j*WAS;
            __half2 a0=*(__half2*)&a[0], a1=*(__half2*)&a[1],
                    a2=*(__half2*)&a[2], a3=*(__half2*)&a[3];
            __half2 be = __hfma2(f5h,a2, __hfma2(f3h,a1, __hmul2(f1h,a0)));
            __half2 bo = __hfma2(f6h,a3, __hfma2(f4h,a2,
                          __hfma2(f2h,a1, __hmul2(f0h,a0))));
            __half2 Pe, Po;
            if (EDGE) {
                bool valid = (j >= jlo) && (j < jhi);
                Pe = valid ? be : NEG2;
                Po = valid ? bo : NEG2;
            } else { Pe = be; Po = bo; }
            __half2 Ae = __hmax2(PeP, h2shift(PeP, Pe));
            __half2 Ao = __hmax2(PoP, h2shift(PoP, Po));
            if (j >= 2) {
                __half2 Me = __hmax2(AeP, __hmax2(Ae, Pe));
                __half2 Mo = __hmax2(AoP, __hmax2(Ao, Po));
                uint2 mm = make_uint2(*(unsigned*)&Me, *(unsigned*)&Mo);
                *reinterpret_cast<uint2*>(mrow + (j - 2)*WMS2) = mm;
            }
            AeP = Ae; AoP = Ao; PeP = Pe; PoP = Po;
        }
    }
    __syncthreads();
}

__global__ void __launch_bounds__(NTHREADS, 4)
aamaxpool_fused_kernel(const float* __restrict__ x,
                       const float* __restrict__ fpre,
                       const float* __restrict__ fpost,
                       float* __restrict__ out)
{
    extern __shared__ unsigned smu[];
    unsigned* sMh = smu + OFF_M;
    unsigned* sA2 = smu + OFF_A;

    const int t  = threadIdx.x;
    const int i0 = blockIdx.x * TI;
    const int nc0 = 2 * blockIdx.y;
    const int in_row0 = 2*i0 - 3;
    const int u0 = 4*i0 - 4;
    const int r0 = 4*i0 - 3;
    const unsigned NEG2U = 0xFC00FC00u;
    const bool edge = (blockIdx.x == 0) | (blockIdx.x == 6);

    const float f0=__ldg(fpre+0), f1=__ldg(fpre+1), f2=__ldg(fpre+2),
                f3=__ldg(fpre+3), f4=__ldg(fpre+4), f5=__ldg(fpre+5),
                f6=__ldg(fpre+6);
    const __half2 f0h=__float2half2_rn(f0), f1h=__float2half2_rn(f1),
                  f2h=__float2half2_rn(f2), f3h=__float2half2_rn(f3),
                  f4h=__float2half2_rn(f4), f5h=__float2half2_rn(f5),
                  f6h=__float2half2_rn(f6);

    // ---- sM halo pads: colwords {0..3, 228..231} x 18 packs x 2 imgs ----
    for (int idx = t; idx < 2*PM*8; idx += NTHREADS) {
        int im = idx / (PM*8), rem = idx - im*(PM*8);
        int jm = rem >> 3, k = rem & 7;
        int c = (k < 4) ? k : 224 + k;
        sMh[im*M_WORDS + jm*WMS2 + swz(c)] = NEG2U;
    }

    if (edge) {
        stage12<true >(sA2, sMh, x, nc0, t, in_row0, u0,
                       f0,f1,f2,f3,f4,f5,f6, f0h,f1h,f2h,f3h,f4h,f5h,f6h);
        // edge fix-up: zero M rows with rg outside [0,222) (FIR zero-pad)
        int btop = (-r0 > 0) ? -r0 : 0;
        int lc0 = 222 - r0; if (lc0 > 35) lc0 = 35;
        if (btop > 0 || lc0 < 35) {
            for (int idx = t; idx < 2*WMS2; idx += NTHREADS) {
                int im = idx / WMS2, c = idx - WMS2*im;
                unsigned* Mi = sMh + im*M_WORDS;
                int cw = swz(c);
                for (int lc = 0; lc < btop; lc++)
                    ((unsigned short*)(Mi + (lc>>1)*WMS2 + cw))[lc & 1] = 0;
                for (int lc = lc0; lc < 35; lc++)
                    ((unsigned short*)(Mi + (lc>>1)*WMS2 + cw))[lc & 1] = 0;
            }
            __syncthreads();
        }
    } else {
        stage12<false>(sA2, sMh, x, nc0, t, in_row0, u0,
                       f0,f1,f2,f3,f4,f5,f6, f0h,f1h,f2h,f3h,f4h,f5h,f6h);
    }

    // ---- stage 3: packed 5-col max + vertical FIR + shfl horizontal FIR ----
    {
        float g[7];
#pragma unroll
        for (int i = 0; i < 7; i++) g[i] = __ldg(fpost + i);

        const int wid = t >> 5, lane = t & 31;
        const int img = wid >> 2;                  // warps 0-3 img0, 4-7 img1
        const int lp  = wid & 3;                   // output rows 2lp, 2lp+1
        const int q   = (lane < 28) ? lane : 27;
        const unsigned* Mi = sMh + img*M_WORDS;
        float d0[8] = {0,0,0,0,0,0,0,0};
        float d1[8] = {0,0,0,0,0,0,0,0};
#pragma unroll
        for (int pp = 0; pp < 6; pp++) {
            const int pg = 4*lp + pp;
            const unsigned* base = Mi + pg*WMS2;
            unsigned Cw[16];
#pragma unroll
            for (int gi = 0; gi < 4; gi++) {
                uint4 v = *reinterpret_cast<const uint4*>(base + swz(8*q + 4*gi));
                Cw[4*gi+0] = v.x; Cw[4*gi+1] = v.y; Cw[4*gi+2] = v.z; Cw[4*gi+3] = v.w;
            }
            __half2 C[16];
#pragma unroll
            for (int i = 0; i < 16; i++) C[i] = *(__half2*)&Cw[i];
            __half2 p[10];                          // p[i-3] = max(C[i],C[i+1])
#pragma unroll
            for (int i = 0; i < 10; i++) p[i] = __hmax2(C[i+3], C[i+4]);
#pragma unroll
            for (int k = 0; k < 8; k++) {
                __half2 wmx = __hmax2(p[k], __hmax2(p[k+2], C[k+7]));
                float lo = __low2float(wmx);
                float hi = __high2float(wmx);
                if (pp == 0)      { d0[k] += g[0]*lo + g[1]*hi; }
                else if (pp == 1) { d0[k] += g[2]*lo + g[3]*hi; }
                else if (pp == 2) { d0[k] += g[4]*lo + g[5]*hi;
                                    d1[k] += g[0]*lo + g[1]*hi; }
                else if (pp == 3) { d0[k] += g[6]*lo;
                                    d1[k] += g[2]*lo + g[3]*hi; }
                else if (pp == 4) { d1[k] += g[4]*lo + g[5]*hi; }
                else              { d1[k] += g[6]*lo; }
            }
        }
        if (q == 27) { d0[6]=0.f; d0[7]=0.f; d1[6]=0.f; d1[7]=0.f; }

        float n5a = __shfl_up_sync(0xffffffffu, d0[5], 1);
        float n6a = __shfl_up_sync(0xffffffffu, d0[6], 1);
        float n7a = __shfl_up_sync(0xffffffffu, d0[7], 1);
        float n5b = __shfl_up_sync(0xffffffffu, d1[5], 1);
        float n6b = __shfl_up_sync(0xffffffffu, d1[6], 1);
        float n7b = __shfl_up_sync(0xffffffffu, d1[7], 1);
        if (q == 0) { n5a=0.f; n6a=0.f; n7a=0.f; n5b=0.f; n6b=0.f; n7b=0.f; }

        float oe0 = g[0]*n5a + g[1]*n6a + g[2]*n7a
                  + g[3]*d0[0] + g[4]*d0[1] + g[5]*d0[2] + g[6]*d0[3];
        float oo0 = g[0]*d0[1] + g[1]*d0[2] + g[2]*d0[3] + g[3]*d0[4]
                  + g[4]*d0[5] + g[5]*d0[6] + g[6]*d0[7];
        float oe1 = g[0]*n5b + g[1]*n6b + g[2]*n7b
                  + g[3]*d1[0] + g[4]*d1[1] + g[5]*d1[2] + g[6]*d1[3];
        float oo1 = g[0]*d1[1] + g[1]*d1[2] + g[2]*d1[3] + g[3]*d1[4]
                  + g[4]*d1[5] + g[5]*d1[6] + g[6]*d1[7];

        if (lane < 28) {
            float* ob = out + (size_t)(nc0 + img)*(HOUT*WOUT)
                            + (size_t)(i0 + 2*lp)*WOUT + 2*q;
            *reinterpret_cast<float2*>(ob)        = make_float2(oe0, oo0);
            *reinterpret_cast<float2*>(ob + WOUT) = make_float2(oe1, oo1);
        }
    }
}

extern "C" void kernel_launch(void* const* d_in, const int* in_sizes, int n_in,
                              void* d_out, int out_size)
{
    const float* x     = (const float*)d_in[0];   // (32,64,112,112)
    const float* fpre  = (const float*)d_in[1];   // (7,)
    const float* fpost = (const float*)d_in[2];   // (7,)
    float* out = (float*)d_out;                   // (32,64,56,56)

    const size_t smem_bytes = SMEM_WORDS * sizeof(unsigned); // 51968
    cudaFuncSetAttribute(aamaxpool_fused_kernel,
                         cudaFuncAttributeMaxDynamicSharedMemorySize,
                         (int)smem_bytes);

    dim3 grid(HOUT / TI, 32 * 64 / 2);   // 7 strips x 1024 image-pairs
    aamaxpool_fused_kernel<<<grid, NTHREADS, smem_bytes>>>(x, fpre, fpost, out);
}